// round 1
// baseline (speedup 1.0000x reference)
#include <cuda_runtime.h>

#define LOG2E 1.4426950408889634f
#define LN2   0.6931471805599453f

// per-batch partial results (allocation-free scratch)
__device__ float g_partial[1024];

static __device__ __forceinline__ float ex2f_(float x) {
    float y; asm("ex2.approx.ftz.f32 %0, %1;" : "=f"(y) : "f"(x)); return y;
}
static __device__ __forceinline__ float lg2f_(float x) {
    float y; asm("lg2.approx.ftz.f32 %0, %1;" : "=f"(y) : "f"(x)); return y;
}
static __device__ __forceinline__ float rcpf_(float x) {
    float y; asm("rcp.approx.ftz.f32 %0, %1;" : "=f"(y) : "f"(x)); return y;
}
static __device__ __forceinline__ unsigned long long pack2_(float lo, float hi) {
    unsigned long long d;
    asm("mov.b64 %0, {%1, %2};" : "=l"(d) : "f"(lo), "f"(hi));
    return d;
}
static __device__ __forceinline__ unsigned long long fma2_(unsigned long long a,
                                                           unsigned long long b,
                                                           unsigned long long c) {
    unsigned long long d;
    asm("fma.rn.f32x2 %0, %1, %2, %3;" : "=l"(d) : "l"(a), "l"(b), "l"(c));
    return d;
}
static __device__ __forceinline__ unsigned long long addx2_(unsigned long long a,
                                                            unsigned long long b) {
    unsigned long long d;
    asm("add.rn.f32x2 %0, %1, %2;" : "=l"(d) : "l"(a), "l"(b));
    return d;
}
static __device__ __forceinline__ void unpack2_(unsigned long long v, float& lo, float& hi) {
    asm("mov.b64 {%0, %1}, %2;" : "=f"(lo), "=f"(hi) : "l"(v));
}

// One CTA per batch element, 64 threads (one per CRF state j).
// Linear-domain forward scan with per-step renormalization by v_0.
__global__ __launch_bounds__(64, 1) void crf_scan_kernel(
    const float* __restrict__ pot,     // [B, T, 64]
    const int*   __restrict__ tags,    // [B, T]
    const int*   __restrict__ seqlen,  // [B]
    const float* __restrict__ K,       // [64, 64]
    const float* __restrict__ sw,      // [B]
    int T)
{
    const int b = blockIdx.x;
    const int j = threadIdx.x;  // 0..63

    __shared__ __align__(16) float wbuf[2][64];
    __shared__ float scal[2];
    __shared__ float sred[64];

    int L = seqlen[b];
    if (L > T) L = T;
    if (L < 0) L = 0;

    const float* potb = pot  + (size_t)b * T * 64;
    const int*   tagb = tags + (size_t)b * T;

    // ---------------- sequence score (gathers) ----------------
    float acc = 0.f;
    for (int t = j; t < T; t += 64) {
        if (t < L) {
            int tg = tagb[t];
            acc += __ldg(potb + (size_t)t * 64 + tg);
            if (t >= 1) acc += __ldg(K + tagb[t - 1] * 64 + tg);
        }
    }
    sred[j] = acc;

    // ---------------- load E column E[i][j] = exp(K[i][j]) into registers ----------------
    unsigned long long e2[32];  // e2[m] = {E[2m][j], E[2m+1][j]} packed f32x2
#pragma unroll
    for (int m = 0; m < 32; m++) {
        float klo = K[(2 * m) * 64 + j];
        float khi = K[(2 * m + 1) * 64 + j];
        e2[m] = pack2_(ex2f_(klo * LOG2E), ex2f_(khi * LOG2E));
    }

    // ---------------- init: alpha_j(0) = pot[b,0,j]  ->  v_j = 2^(pot*log2e) ----------------
    float v0 = ex2f_(potb[j] * LOG2E);
    wbuf[0][j] = v0;
    if (j == 0) scal[0] = v0;
    __syncthreads();

    float seqscore = 0.f;
    if (j == 0) {
        float s = 0.f;
#pragma unroll
        for (int i = 0; i < 64; i++) s += sred[i];
        seqscore = s;
    }

    // ---------------- forward scan, t = 1 .. L-1 ----------------
    // Invariant: alpha_j(t) = ln2*loff + ln(wbuf[cur][j])   (loff in log2 units)
    float loff = 0.f;
    int cur = 0;

    // register prefetch pipeline, distance 4
    float pf[4];
#pragma unroll
    for (int u = 0; u < 4; u++)
        pf[u] = (1 + u < T) ? potb[(size_t)(1 + u) * 64 + j] : 0.f;

    int t = 1;
    while (t < L) {
#pragma unroll
        for (int u = 0; u < 4; u++) {
            if (t < L) {  // uniform per block -> barrier inside is safe
                float D  = scal[cur];       // v_0 from previous step
                float rD = rcpf_(D);
                float p  = ex2f_(pf[u] * LOG2E);
                loff += lg2f_(D);
                // prefetch potential for t+4
                pf[u] = (t + 4 < T) ? potb[(size_t)(t + 4) * 64 + j] : 0.f;

                // s_j = sum_i w_i * E[i][j]  (64 MACs as 32 packed FFMA2)
                const ulonglong2* wv = (const ulonglong2*)&wbuf[cur][0];
                unsigned long long a0 = 0ull, a1 = 0ull, a2 = 0ull, a3 = 0ull;
#pragma unroll
                for (int k = 0; k < 8; k++) {
                    ulonglong2 q0 = wv[2 * k];
                    ulonglong2 q1 = wv[2 * k + 1];
                    a0 = fma2_(q0.x, e2[4 * k + 0], a0);
                    a1 = fma2_(q0.y, e2[4 * k + 1], a1);
                    a2 = fma2_(q1.x, e2[4 * k + 2], a2);
                    a3 = fma2_(q1.y, e2[4 * k + 3], a3);
                }
                unsigned long long s01 = addx2_(a0, a1);
                unsigned long long s23 = addx2_(a2, a3);
                float slo, shi;
                unpack2_(addx2_(s01, s23), slo, shi);

                float vnew = (slo + shi) * rD * p;
                int ncur = cur ^ 1;
                wbuf[ncur][j] = vnew;
                if (j == 0) scal[ncur] = vnew;
                __syncthreads();
                cur = ncur;
                t++;
            }
        }
    }

    // ---------------- finalize this batch ----------------
    if (j == 0) {
        float sum = 0.f;
#pragma unroll
        for (int i = 0; i < 64; i++) sum += wbuf[cur][i];
        float log_norm = (loff + lg2f_(sum)) * LN2;
        float ll = seqscore - log_norm;
        g_partial[b] = -ll * sw[b];
    }
}

__global__ void crf_finalize_kernel(float* __restrict__ out, int B) {
    __shared__ float sh[256];
    int tid = threadIdx.x;
    float v = 0.f;
    for (int i = tid; i < B; i += 256) v += g_partial[i];
    sh[tid] = v;
    __syncthreads();
    for (int s = 128; s > 0; s >>= 1) {
        if (tid < s) sh[tid] += sh[tid + s];
        __syncthreads();
    }
    if (tid == 0) out[0] = sh[0] / (float)B;
}

extern "C" void kernel_launch(void* const* d_in, const int* in_sizes, int n_in,
                              void* d_out, int out_size) {
    const float* pot    = (const float*)d_in[0];
    const int*   tags   = (const int*)d_in[1];
    const int*   seqlen = (const int*)d_in[2];
    const float* K      = (const float*)d_in[3];
    const float* sw     = (const float*)d_in[4];

    int B = in_sizes[2];            // sequence_length element count
    int T = in_sizes[1] / B;        // tags is [B, T]

    crf_scan_kernel<<<B, 64>>>(pot, tags, seqlen, K, sw, T);
    crf_finalize_kernel<<<1, 256>>>((float*)d_out, B);
}

// round 2
// speedup vs baseline: 1.0828x; 1.0828x over previous
#include <cuda_runtime.h>

#define LOG2E 1.4426950408889634f
#define LN2   0.6931471805599453f

__device__ float g_partial[1024];
__device__ unsigned int g_count = 0;

static __device__ __forceinline__ float ex2f_(float x) {
    float y; asm("ex2.approx.ftz.f32 %0, %1;" : "=f"(y) : "f"(x)); return y;
}
static __device__ __forceinline__ float lg2f_(float x) {
    float y; asm("lg2.approx.ftz.f32 %0, %1;" : "=f"(y) : "f"(x)); return y;
}
static __device__ __forceinline__ float rcpf_(float x) {
    float y; asm("rcp.approx.ftz.f32 %0, %1;" : "=f"(y) : "f"(x)); return y;
}
static __device__ __forceinline__ unsigned long long pack2_(float lo, float hi) {
    unsigned long long d;
    asm("mov.b64 %0, {%1, %2};" : "=l"(d) : "f"(lo), "f"(hi));
    return d;
}
static __device__ __forceinline__ unsigned long long fma2_(unsigned long long a,
                                                           unsigned long long b,
                                                           unsigned long long c) {
    unsigned long long d;
    asm("fma.rn.f32x2 %0, %1, %2, %3;" : "=l"(d) : "l"(a), "l"(b), "l"(c));
    return d;
}
static __device__ __forceinline__ unsigned long long addx2_(unsigned long long a,
                                                            unsigned long long b) {
    unsigned long long d;
    asm("add.rn.f32x2 %0, %1, %2;" : "=l"(d) : "l"(a), "l"(b));
    return d;
}
static __device__ __forceinline__ void unpack2_(unsigned long long v, float& lo, float& hi) {
    asm("mov.b64 {%0, %1}, %2;" : "=f"(lo), "=f"(hi) : "l"(v));
}

// One step of the linear-domain forward recurrence (branch-free).
// Invariant: alpha_j = LN2*loff + ln(wbuf[cur][j])
#define STEP(UU)                                                        \
    {                                                                   \
        float D  = scal[cur];                                           \
        float rD = rcpf_(D);                                            \
        loff += lg2f_(D);                                               \
        float p  = ex2f_(pf[UU] * LOG2E);                               \
        pf[UU] = *potp;                                                 \
        potp += 64;                                                     \
        if (potp > potend) potp = potend;                               \
        const ulonglong2* wv = (const ulonglong2*)&wbuf[cur][0];        \
        unsigned long long a0 = 0ull, a1 = 0ull, a2 = 0ull, a3 = 0ull;  \
        _Pragma("unroll")                                               \
        for (int k2 = 0; k2 < 8; k2++) {                                \
            ulonglong2 q0 = wv[2 * k2];                                 \
            ulonglong2 q1 = wv[2 * k2 + 1];                             \
            a0 = fma2_(q0.x, e2[4 * k2 + 0], a0);                       \
            a1 = fma2_(q0.y, e2[4 * k2 + 1], a1);                       \
            a2 = fma2_(q1.x, e2[4 * k2 + 2], a2);                       \
            a3 = fma2_(q1.y, e2[4 * k2 + 3], a3);                       \
        }                                                               \
        float slo, shi;                                                 \
        unpack2_(addx2_(addx2_(a0, a1), addx2_(a2, a3)), slo, shi);     \
        float vnew = (slo + shi) * (rD * p);                            \
        int ncur = cur ^ 1;                                             \
        wbuf[ncur][j] = vnew;                                           \
        if (j == 0) scal[ncur] = vnew;                                  \
        __syncthreads();                                                \
        cur = ncur;                                                     \
    }

// One CTA per batch element, 64 threads (one per CRF state j).
__global__ __launch_bounds__(64, 1) void crf_scan_kernel(
    const float* __restrict__ pot,     // [B, T, 64]
    const int*   __restrict__ tags,    // [B, T]
    const int*   __restrict__ seqlen,  // [B]
    const float* __restrict__ K,       // [64, 64]
    const float* __restrict__ sw,      // [B]
    float*       __restrict__ out,
    int T)
{
    const int b = blockIdx.x;
    const int j = threadIdx.x;  // 0..63

    __shared__ __align__(16) float wbuf[2][64];
    __shared__ float scal[2];
    __shared__ float sred[64];
    __shared__ int   stags[1024];

    int L = seqlen[b];
    if (L > T) L = T;
    if (L < 1) L = 1;

    const float* potb = pot  + (size_t)b * T * 64;
    const int*   tagb = tags + (size_t)b * T;

    // ---- stage tags through shared so gathers are fully independent ----
    for (int t = j; t < T; t += 64) stags[t] = tagb[t];
    __syncthreads();

    // ---- sequence score (high-MLP gathers) ----
    float acc = 0.f;
    for (int t = j; t < T; t += 64) {
        if (t < L) {
            int tg = stags[t];
            acc += __ldg(potb + (size_t)t * 64 + tg);
            if (t >= 1) acc += __ldg(K + stags[t - 1] * 64 + tg);
        }
    }
    sred[j] = acc;

    // ---- E column: e2[m] = {exp(K[2m][j]), exp(K[2m+1][j])} ----
    unsigned long long e2[32];
#pragma unroll
    for (int m = 0; m < 32; m++) {
        float klo = K[(2 * m) * 64 + j];
        float khi = K[(2 * m + 1) * 64 + j];
        e2[m] = pack2_(ex2f_(klo * LOG2E), ex2f_(khi * LOG2E));
    }

    // ---- init ----
    float v0 = ex2f_(potb[j] * LOG2E);
    wbuf[0][j] = v0;
    if (j == 0) scal[0] = v0;
    __syncthreads();

    float loff = 0.f;
    int cur = 0;

    // prefetch ring: pf[u] holds pot row (t_next + u) for the next 4 steps
    float pf[4];
#pragma unroll
    for (int u = 0; u < 4; u++) {
        int row = 1 + u; if (row > T - 1) row = T - 1;
        pf[u] = potb[(size_t)row * 64 + j];
    }
    const float* potend = potb + (size_t)(T - 1) * 64 + j;
    const float* potp   = potb + (size_t)5 * 64 + j;
    if (potp > potend) potp = potend;

    // ---- branch-free main loop ----
    int nsteps = L - 1;
    int n4 = nsteps >> 2;
    for (int it = 0; it < n4; it++) {
        STEP(0) STEP(1) STEP(2) STEP(3)
    }
    int rem = nsteps & 3;
    if (rem > 0) STEP(0)
    if (rem > 1) STEP(1)
    if (rem > 2) STEP(2)

    // ---- finalize this batch + fused global reduction (last block) ----
    if (j == 0) {
        float sum = 0.f;
#pragma unroll
        for (int i = 0; i < 64; i++) sum += wbuf[cur][i];
        float seqs = 0.f;
#pragma unroll
        for (int i = 0; i < 64; i++) seqs += sred[i];
        float log_norm = (loff + lg2f_(sum)) * LN2;
        g_partial[b] = -(seqs - log_norm) * sw[b];
        __threadfence();
        unsigned int old = atomicAdd(&g_count, 1);
        if (old == gridDim.x - 1) {
            g_count = 0;                 // reset for next graph replay
            __threadfence();
            float tot = 0.f;
            int nB = gridDim.x;
#pragma unroll 8
            for (int i = 0; i < nB; i++) tot += g_partial[i];
            *out = tot / (float)nB;
        }
    }
}

extern "C" void kernel_launch(void* const* d_in, const int* in_sizes, int n_in,
                              void* d_out, int out_size) {
    const float* pot    = (const float*)d_in[0];
    const int*   tags   = (const int*)d_in[1];
    const int*   seqlen = (const int*)d_in[2];
    const float* K      = (const float*)d_in[3];
    const float* sw     = (const float*)d_in[4];

    int B = in_sizes[2];            // sequence_length element count
    int T = in_sizes[1] / B;        // tags is [B, T]

    crf_scan_kernel<<<B, 64>>>(pot, tags, seqlen, K, sw, (float*)d_out, T);
}

// round 3
// speedup vs baseline: 1.2154x; 1.1225x over previous
#include <cuda_runtime.h>

#define LOG2E 1.4426950408889634f
#define LN2   0.6931471805599453f

__device__ float g_partial[1024];
__device__ unsigned int g_count = 0;

static __device__ __forceinline__ float ex2f_(float x) {
    float y; asm("ex2.approx.ftz.f32 %0, %1;" : "=f"(y) : "f"(x)); return y;
}
static __device__ __forceinline__ float lg2f_(float x) {
    float y; asm("lg2.approx.ftz.f32 %0, %1;" : "=f"(y) : "f"(x)); return y;
}
static __device__ __forceinline__ unsigned long long pack2_(float lo, float hi) {
    unsigned long long d;
    asm("mov.b64 %0, {%1, %2};" : "=l"(d) : "f"(lo), "f"(hi));
    return d;
}
static __device__ __forceinline__ unsigned long long fma2_(unsigned long long a,
                                                           unsigned long long b,
                                                           unsigned long long c) {
    unsigned long long d;
    asm("fma.rn.f32x2 %0, %1, %2, %3;" : "=l"(d) : "l"(a), "l"(b), "l"(c));
    return d;
}
static __device__ __forceinline__ unsigned long long addx2_(unsigned long long a,
                                                            unsigned long long b) {
    unsigned long long d;
    asm("add.rn.f32x2 %0, %1, %2;" : "=l"(d) : "l"(a), "l"(b));
    return d;
}
static __device__ __forceinline__ void unpack2_(unsigned long long v, float& lo, float& hi) {
    asm("mov.b64 {%0, %1}, %2;" : "=f"(lo), "=f"(hi) : "l"(v));
}

// ---- the 32-MAC half-contraction + pair combine (CUR is a literal) ----
#define MACS(CUR)                                                       \
    const ulonglong2* wv = (const ulonglong2*)(&wb[CUR][0] + 40 * h);   \
    unsigned long long a0 = 0ull, a1 = 0ull, a2 = 0ull, a3 = 0ull;      \
    _Pragma("unroll")                                                   \
    for (int k = 0; k < 8; k += 2) {                                    \
        ulonglong2 q0 = wv[k];                                          \
        ulonglong2 q1 = wv[k + 1];                                      \
        a0 = fma2_(q0.x, e2[2 * k + 0], a0);                            \
        a1 = fma2_(q0.y, e2[2 * k + 1], a1);                            \
        a2 = fma2_(q1.x, e2[2 * k + 2], a2);                            \
        a3 = fma2_(q1.y, e2[2 * k + 3], a3);                            \
    }                                                                   \
    float lo_, hi_;                                                     \
    unpack2_(addx2_(addx2_(a0, a2), addx2_(a1, a3)), lo_, hi_);         \
    float part = lo_ + hi_;                                             \
    float s = part + __shfl_xor_sync(0xffffffffu, part, 1);

// normalizing step (divide by previous v0, folded into the ex2)
#define STEP_N(UU, CUR)                                                 \
    {                                                                   \
        float D   = scal[CUR];                                          \
        float l2D = lg2f_(D);                                           \
        loff += l2D;                                                    \
        float p = ex2f_(fmaf(pf[UU], LOG2E, -l2D));                     \
        pf[UU] = *(const float*)(potc + off);                           \
        off = min(off + 256, offmax);                                   \
        MACS(CUR)                                                       \
        float vnew = s * p;                                             \
        if (h == 0)   wb[(CUR) ^ 1][wslot] = vnew;                      \
        if (tid == 0) scal[(CUR) ^ 1] = vnew;                           \
        __syncthreads();                                                \
    }

// free step (no renormalization)
#define STEP_F(UU, CUR)                                                 \
    {                                                                   \
        float p = ex2f_(pf[UU] * LOG2E);                                \
        pf[UU] = *(const float*)(potc + off);                           \
        off = min(off + 256, offmax);                                   \
        MACS(CUR)                                                       \
        float vnew = s * p;                                             \
        if (h == 0)   wb[(CUR) ^ 1][wslot] = vnew;                      \
        if (tid == 0) scal[(CUR) ^ 1] = vnew;                           \
        __syncthreads();                                                \
    }

// One CTA per batch element. 128 threads: thread = (j = tid>>1, h = tid&1).
// Thread (j,h) contracts i in [32h, 32h+32); pair combines via shfl.bfly(1).
__global__ __launch_bounds__(128, 1) void crf_scan_kernel(
    const float* __restrict__ pot,     // [B, T, 64]
    const int*   __restrict__ tags,    // [B, T]
    const int*   __restrict__ seqlen,  // [B]
    const float* __restrict__ K,       // [64, 64]
    const float* __restrict__ sw,      // [B]
    float*       __restrict__ out,
    int T)
{
    const int b   = blockIdx.x;
    const int tid = threadIdx.x;
    const int j   = tid >> 1;   // 0..63  (state)
    const int h   = tid & 1;    // 0..1   (i-half)

    // w split: lower 32 floats at +0, upper 32 at +40 floats (160B -> bank offset 8)
    __shared__ __align__(16) float wb[2][80];
    __shared__ float scal[2];
    __shared__ float sred[128];
    __shared__ int   stags[1024];

    int L = seqlen[b];
    if (L > T) L = T;
    if (L < 1) L = 1;

    const float* potb = pot  + (size_t)b * T * 64;
    const int*   tagb = tags + (size_t)b * T;

    // ---- stage tags ----
    for (int t = tid; t < T; t += 128) stags[t] = tagb[t];
    __syncthreads();

    // ---- sequence score gathers (high MLP) ----
    float acc = 0.f;
    for (int t = tid; t < T; t += 128) {
        if (t < L) {
            int tg = stags[t];
            acc += __ldg(potb + (size_t)t * 64 + tg);
            if (t >= 1) acc += __ldg(K + stags[t - 1] * 64 + tg);
        }
    }
    sred[tid] = acc;

    // ---- E block for this thread: e2[m] = {exp(K[i0+2m][j]), exp(K[i0+2m+1][j])}, i0=32h ----
    unsigned long long e2[16];
#pragma unroll
    for (int m = 0; m < 16; m++) {
        int i0 = 32 * h + 2 * m;
        e2[m] = pack2_(ex2f_(K[i0 * 64 + j] * LOG2E),
                       ex2f_(K[(i0 + 1) * 64 + j] * LOG2E));
    }

    const int wslot = (j < 32) ? j : (40 + j - 32);

    // ---- init w(0) ----
    if (h == 0) {
        float v0 = ex2f_(potb[j] * LOG2E);
        wb[0][wslot] = v0;
        if (j == 0) scal[0] = v0;
    }
    __syncthreads();

    // ---- prefetch ring (depth 4), clamped byte offsets ----
    const char* potc = (const char*)potb;
    const int offmax = (T - 1) * 256 + j * 4;
    float pf[4];
#pragma unroll
    for (int u = 0; u < 4; u++) {
        int row = 1 + u; if (row > T - 1) row = T - 1;
        pf[u] = potb[(size_t)row * 64 + j];
    }
    int off = 5 * 256 + j * 4;
    if (off > offmax) off = offmax;

    float loff = 0.f;

    // ---- main loop: 4 steps/iter, compile-time ping-pong, renorm every 2nd ----
    const int nsteps = L - 1;
    int n4 = nsteps >> 2;
    for (int it = 0; it < n4; it++) {
        STEP_N(0, 0) STEP_F(1, 1) STEP_N(2, 0) STEP_F(3, 1)
    }
    const int rem = nsteps & 3;
    if (rem > 0) STEP_N(0, 0)
    if (rem > 1) STEP_F(1, 1)
    if (rem > 2) STEP_N(2, 0)

    // ---- finalize + fused reduction ----
    if (tid == 0) {
        const int fin = nsteps & 1;
        float sum = 0.f;
#pragma unroll
        for (int i = 0; i < 32; i++) sum += wb[fin][i];
#pragma unroll
        for (int i = 0; i < 32; i++) sum += wb[fin][40 + i];
        float seqs = 0.f;
#pragma unroll
        for (int i = 0; i < 128; i++) seqs += sred[i];
        float log_norm = (loff + lg2f_(sum)) * LN2;
        g_partial[b] = -(seqs - log_norm) * sw[b];
        __threadfence();
        unsigned int old = atomicAdd(&g_count, 1);
        if (old == gridDim.x - 1) {
            g_count = 0;               // reset for next graph replay
            __threadfence();
            float tot = 0.f;
            int nB = gridDim.x;
#pragma unroll 8
            for (int i = 0; i < nB; i++) tot += g_partial[i];
            *out = tot / (float)nB;
        }
    }
}

extern "C" void kernel_launch(void* const* d_in, const int* in_sizes, int n_in,
                              void* d_out, int out_size) {
    const float* pot    = (const float*)d_in[0];
    const int*   tags   = (const int*)d_in[1];
    const int*   seqlen = (const int*)d_in[2];
    const float* K      = (const float*)d_in[3];
    const float* sw     = (const float*)d_in[4];

    int B = in_sizes[2];            // sequence_length element count
    int T = in_sizes[1] / B;        // tags is [B, T]

    crf_scan_kernel<<<B, 128>>>(pot, tags, seqlen, K, sw, (float*)d_out, T);
}